// round 14
// baseline (speedup 1.0000x reference)
#include <cuda_runtime.h>
#include <cfloat>

// ChamferDistance: x,y = [16, 4096, 3] fp32 -> scalar
// R14 = R13 (y-sorted window NN + chunked work queue + atomicMin merge) with
//   (a) db sorting hoisted into a separate 32-block kernel writing global
//       scratch (was redone 4x by every split block), and
//   (b) warp-shuffle block scans (3 barriers) replacing the 18-barrier
//       ripple scans.

#define NB      16
#define NPTS    4096
#define SPLITS  4
#define QPB     (NPTS / SPLITS)   // 1024 queries per block
#define THREADS 512
#define NWARP   (THREADS / 32)    // 16
#define GSIZE   64
#define NGRPB   (QPB / GSIZE)     // 16 groups per block (== NWARP)
#define NBLOCKS (NB * 2 * SPLITS) // 128
#define NBD     (NB * 2)          // 32 (batch, dir) pairs
#define NBIN    1024
#define BPT     (NBIN / THREADS)  // 2
#define CENT    256
#define CHUNK   512
#define MAXCH   256

__device__ float g_partial[NBLOCKS];
__device__ unsigned int g_ticket;       // zero-init; reset by last block

// Pre-sorted db scratch (written by sort_kernel, read by chamfer_kernel).
__device__ float g_sxa[NBD][NPTS];
__device__ float g_sya[NBD][NPTS];
__device__ float g_sza[NBD][NPTS];
__device__ float g_swa[NBD][NPTS];
__device__ int   g_dboff[NBD][NBIN + 1];
__device__ float g_meta[NBD][2];        // ymin, W

typedef unsigned long long ull;

__device__ __forceinline__ ull pack2(float a, float b) {
    ull r; asm("mov.b64 %0, {%1, %2};" : "=l"(r) : "f"(a), "f"(b)); return r;
}
__device__ __forceinline__ ull fma2(ull a, ull b, ull c) {
    ull d; asm("fma.rn.f32x2 %0, %1, %2, %3;" : "=l"(d) : "l"(a), "l"(b), "l"(c)); return d;
}
__device__ __forceinline__ void unpack2(ull v, float& lo, float& hi) {
    asm("mov.b64 {%0, %1}, %2;" : "=f"(lo), "=f"(hi) : "l"(v));
}
__device__ __forceinline__ unsigned int fenc(float f) {
    unsigned int u = __float_as_uint(f);
    return u ^ (((int)u >> 31) | 0x80000000u);
}
__device__ __forceinline__ float fdec(unsigned int e) {
    unsigned int u = (e & 0x80000000u) ? (e ^ 0x80000000u) : ~e;
    return __uint_as_float(u);
}

// Block-wide exclusive prefix sum of val (tid order). 3 barriers.
__device__ __forceinline__ int block_exscan(int val, int wid, int lid, int* ws) {
    __syncthreads();                      // protect ws reuse
    int incl = val;
#pragma unroll
    for (int o = 1; o < 32; o <<= 1) {
        int n = __shfl_up_sync(0xFFFFFFFFu, incl, o);
        if (lid >= o) incl += n;
    }
    if (lid == 31) ws[wid] = incl;
    __syncthreads();
    if (wid == 0) {
        int wv = (lid < NWARP) ? ws[lid] : 0;
#pragma unroll
        for (int o = 1; o < NWARP; o <<= 1) {
            int n = __shfl_up_sync(0xFFFFFFFFu, wv, o);
            if (lid >= o) wv += n;
        }
        if (lid < NWARP) ws[lid] = wv;    // inclusive warp sums
    }
    __syncthreads();
    int wpre = (wid > 0) ? ws[wid - 1] : 0;
    return wpre + incl - val;
}

// ------------------------- kernel 1: db sort -------------------------------
__global__ __launch_bounds__(THREADS, 1) void sort_kernel(
    const float* __restrict__ x, const float* __restrict__ y)
{
    __shared__ int   cnt[NBIN];
    __shared__ int   cur[NBIN];
    __shared__ int   ws[NWARP];
    __shared__ float wmm[2][NWARP];
    __shared__ float s_ymin, s_W;

    const int tid = threadIdx.x;
    const int wid = tid >> 5, lid = tid & 31;
    const unsigned FULL = 0xFFFFFFFFu;
    const int bd  = blockIdx.x;           // 2*b + dir
    const int b   = bd >> 1, dir = bd & 1;
    const float* __restrict__ db = (dir ? x : y) + (size_t)b * NPTS * 3;

    float lmin = FLT_MAX, lmax = -FLT_MAX;
    for (int j = tid; j < NPTS; j += THREADS) {
        float py = db[3 * j + 1];
        lmin = fminf(lmin, py); lmax = fmaxf(lmax, py);
    }
#pragma unroll
    for (int o = 16; o > 0; o >>= 1) {
        lmin = fminf(lmin, __shfl_xor_sync(FULL, lmin, o));
        lmax = fmaxf(lmax, __shfl_xor_sync(FULL, lmax, o));
    }
    if (lid == 0) { wmm[0][wid] = lmin; wmm[1][wid] = lmax; }
    for (int c = tid; c < NBIN; c += THREADS) cnt[c] = 0;
    __syncthreads();
    if (tid == 0) {
        float a0 = FLT_MAX, a1 = -FLT_MAX;
#pragma unroll
        for (int w = 0; w < NWARP; w++) {
            a0 = fminf(a0, wmm[0][w]); a1 = fmaxf(a1, wmm[1][w]);
        }
        s_ymin = a0;
        s_W = fmaxf((a1 - a0) / NBIN, 1e-30f);
        g_meta[bd][0] = a0;
        g_meta[bd][1] = s_W;
    }
    __syncthreads();
    const float ymin = s_ymin, inv = 1.0f / s_W;

    for (int j = tid; j < NPTS; j += THREADS) {
        float py = db[3 * j + 1];
        int c = min(max((int)((py - ymin) * inv), 0), NBIN - 1);
        atomicAdd(&cnt[c], 1);
    }
    // scan
    {
        const int base = tid * BPT;
        __syncthreads();
        int c0 = cnt[base], c1 = cnt[base + 1];
        int ex = block_exscan(c0 + c1, wid, lid, ws);
        g_dboff[bd][base]     = ex;
        g_dboff[bd][base + 1] = ex + c0;
        cur[base]     = ex;
        cur[base + 1] = ex + c0;
        if (tid == THREADS - 1) g_dboff[bd][NBIN] = NPTS;
    }
    __syncthreads();
    // scatter to global SoA (intra-bin order irrelevant for the final min)
    for (int j = tid; j < NPTS; j += THREADS) {
        float a = db[3 * j], c = db[3 * j + 1], d = db[3 * j + 2];
        int cb = min(max((int)((c - ymin) * inv), 0), NBIN - 1);
        int pos = atomicAdd(&cur[cb], 1);
        g_sxa[bd][pos] = a; g_sya[bd][pos] = c; g_sza[bd][pos] = d;
        g_swa[bd][pos] = fmaf(a, a, fmaf(c, c, d * d));
    }
}

// ------------------------- kernel 2: chamfer -------------------------------
struct SmemLayout {
    float  sxa[NPTS];
    float  sya[NPTS];
    float  sza[NPTS];
    float  swa[NPTS];
    float4 qpts[QPB];
    int    qidx[QPB];
    unsigned int gdist[QPB];
    int    dboff[NBIN + 1];
    int    qoff[NBIN + 1];
    int    cnt[NBIN];
    int    cur[NBIN];
    int    ws[NWARP];
    int    cg[MAXCH];
    int    clo[MAXCH], chi[MAXCH];
    float  wred[NWARP];
    int    nch;
    int    cctr;
    bool   amlast;
};

#define SCAN_RANGE(JLO, JHI)                                                   \
    _Pragma("unroll 2")                                                        \
    for (int j = (JLO); j < (JHI); j += 4) {                                   \
        const ulonglong2 Xv = *(const ulonglong2*)(s->sxa + j);                \
        const ulonglong2 Yv = *(const ulonglong2*)(s->sya + j);                \
        const ulonglong2 Zv = *(const ulonglong2*)(s->sza + j);                \
        const ulonglong2 Wv = *(const ulonglong2*)(s->swa + j);                \
        ull ta, tb; float e0, e1, f0, f1;                                      \
        ta = fma2(n00, Xv.x, Wv.x); ta = fma2(n10, Yv.x, ta); ta = fma2(n20, Zv.x, ta); \
        tb = fma2(n00, Xv.y, Wv.y); tb = fma2(n10, Yv.y, tb); tb = fma2(n20, Zv.y, tb); \
        unpack2(ta, e0, e1); unpack2(tb, f0, f1);                              \
        m00 = fminf(m00, e0); m00 = fminf(m00, f0);                            \
        m10 = fminf(m10, e1); m10 = fminf(m10, f1);                            \
        ta = fma2(n01, Xv.x, Wv.x); ta = fma2(n11, Yv.x, ta); ta = fma2(n21, Zv.x, ta); \
        tb = fma2(n01, Xv.y, Wv.y); tb = fma2(n11, Yv.y, tb); tb = fma2(n21, Zv.y, tb); \
        unpack2(ta, e0, e1); unpack2(tb, f0, f1);                              \
        m01 = fminf(m01, e0); m01 = fminf(m01, f0);                            \
        m11 = fminf(m11, e1); m11 = fminf(m11, f1);                            \
    }

__global__ __launch_bounds__(THREADS, 1) void chamfer_kernel(
    const float* __restrict__ x, const float* __restrict__ y,
    float* __restrict__ out)
{
    extern __shared__ char sraw[];
    SmemLayout* s = (SmemLayout*)sraw;

    const int tid = threadIdx.x;
    const int wid = tid >> 5, lid = tid & 31;
    const unsigned FULL = 0xFFFFFFFFu;
    const int dir = blockIdx.y;
    const int b   = blockIdx.z;
    const int bd  = 2 * b + dir;
    const float* __restrict__ q = (dir ? y : x) + (size_t)b * NPTS * 3
                                  + (size_t)blockIdx.x * QPB * 3;

    // ---- load pre-sorted db SoA + offsets (coalesced, L2-hot) ----
    for (int j = tid; j < NPTS; j += THREADS) {
        s->sxa[j] = g_sxa[bd][j];
        s->sya[j] = g_sya[bd][j];
        s->sza[j] = g_sza[bd][j];
        s->swa[j] = g_swa[bd][j];
    }
    for (int j = tid; j < NBIN + 1; j += THREADS) s->dboff[j] = g_dboff[bd][j];
    for (int c = tid; c < NBIN; c += THREADS) s->cnt[c] = 0;
    const unsigned ENC_MAX = fenc(FLT_MAX);
    for (int i = tid; i < QPB; i += THREADS) s->gdist[i] = ENC_MAX;
    if (tid == 0) { s->nch = 0; s->cctr = 0; }
    const float ymin = g_meta[bd][0];
    const float W    = g_meta[bd][1];
    const float inv  = 1.0f / W;
    __syncthreads();

    // ---- query histogram + scan + scatter + stable intra-bin fix ----
    for (int j = tid; j < QPB; j += THREADS) {
        float py = q[3 * j + 1];
        int c = min(max((int)((py - ymin) * inv), 0), NBIN - 1);
        atomicAdd(&s->cnt[c], 1);
    }
    {
        const int base = tid * BPT;
        __syncthreads();
        int c0 = s->cnt[base], c1 = s->cnt[base + 1];
        int ex = block_exscan(c0 + c1, wid, lid, s->ws);
        s->qoff[base]     = ex;
        s->qoff[base + 1] = ex + c0;
        s->cur[base]      = ex;
        s->cur[base + 1]  = ex + c0;
        if (tid == THREADS - 1) s->qoff[NBIN] = QPB;
    }
    __syncthreads();
    for (int j = tid; j < QPB; j += THREADS) {
        float a = q[3 * j], c = q[3 * j + 1], d = q[3 * j + 2];
        int cb = min(max((int)((c - ymin) * inv), 0), NBIN - 1);
        int pos = atomicAdd(&s->cur[cb], 1);
        s->qpts[pos] = make_float4(a, c, d, fmaf(a, a, fmaf(c, c, d * d)));
        s->qidx[pos] = j;
    }
    __syncthreads();
    for (int c = tid; c < NBIN; c += THREADS) {   // stable fix (bins tiny)
        int lo = s->qoff[c], hi = s->qoff[c + 1];
        for (int i = lo + 1; i < hi; i++) {
            float4 pv = s->qpts[i]; int iv = s->qidx[i];
            int j2 = i - 1;
            while (j2 >= lo && s->qidx[j2] > iv) {
                s->qpts[j2 + 1] = s->qpts[j2];
                s->qidx[j2 + 1] = s->qidx[j2];
                j2--;
            }
            s->qpts[j2 + 1] = pv; s->qidx[j2 + 1] = iv;
        }
    }
    __syncthreads();

    // ---- Stage A: warp w: group w's slab scan -> bound -> enqueue chunks ----
    {
        const int g = wid;
        const int base = g * GSIZE;
        const float4 Q0 = s->qpts[base + 2 * lid];
        const float4 Q1 = s->qpts[base + 2 * lid + 1];
        const ull n00 = pack2(-2.0f * Q0.x, -2.0f * Q0.x);
        const ull n10 = pack2(-2.0f * Q0.y, -2.0f * Q0.y);
        const ull n20 = pack2(-2.0f * Q0.z, -2.0f * Q0.z);
        const ull n01 = pack2(-2.0f * Q1.x, -2.0f * Q1.x);
        const ull n11 = pack2(-2.0f * Q1.y, -2.0f * Q1.y);
        const ull n21 = pack2(-2.0f * Q1.z, -2.0f * Q1.z);
        float m00 = FLT_MAX, m10 = FLT_MAX, m01 = FLT_MAX, m11 = FLT_MAX;

        const float ylo_g = __shfl_sync(FULL, Q0.y, 0);
        const float yhi_g = __shfl_sync(FULL, Q1.y, 31);
        const float ymid  = 0.5f * (ylo_g + yhi_g);
        const int   cbin  = min(max((int)((ymid - ymin) * inv), 0), NBIN - 1);
        int lo_c = s->dboff[cbin] - CENT / 2;
        lo_c = min(max(lo_c, 0), NPTS - CENT) & ~3;
        const int hi_c = lo_c + CENT;
        SCAN_RANGE(lo_c, hi_c)

        const float da  = fminf(m00, m10) + Q0.w;
        const float dbq = fminf(m01, m11) + Q1.w;
        atomicMin(&s->gdist[base + 2 * lid],     fenc(da));
        atomicMin(&s->gdist[base + 2 * lid + 1], fenc(dbq));

        const float d0 = sqrtf(fmaxf(da, 0.0f));
        const float d1 = sqrtf(fmaxf(dbq, 0.0f));
        float wlo = fminf(Q0.y - d0, Q1.y - d1);
        float whi = fmaxf(Q0.y + d0, Q1.y + d1);
#pragma unroll
        for (int o = 16; o > 0; o >>= 1) {
            wlo = fminf(wlo, __shfl_xor_sync(FULL, wlo, o));
            whi = fmaxf(whi, __shfl_xor_sync(FULL, whi, o));
        }
        const int lob = (int)fmaxf(floorf((wlo - ymin) * inv) - 2.0f, 0.0f);
        const int hib = (int)fminf(floorf((whi - ymin) * inv) + 2.0f, (float)(NBIN - 1));
        const int jlo = s->dboff[lob] & ~3;
        const int jhi = min((s->dboff[hib + 1] + 3) & ~3, NPTS);
        const int preh  = min(lo_c, jhi);
        const int postl = max(hi_c, jlo);

        if (lid == 0) {
            int npre  = (preh > jlo)  ? (preh - jlo + CHUNK - 1) / CHUNK : 0;
            int npost = (jhi > postl) ? (jhi - postl + CHUNK - 1) / CHUNK : 0;
            int slot = atomicAdd(&s->nch, npre + npost);
            for (int k = 0; k < npre; k++) {
                s->cg[slot] = g;
                s->clo[slot] = jlo + k * CHUNK;
                s->chi[slot] = min(jlo + (k + 1) * CHUNK, preh);
                slot++;
            }
            for (int k = 0; k < npost; k++) {
                s->cg[slot] = g;
                s->clo[slot] = postl + k * CHUNK;
                s->chi[slot] = min(postl + (k + 1) * CHUNK, jhi);
                slot++;
            }
        }
    }
    __syncthreads();

    // ---- Stage B: dynamic chunk processing ----
    const int nch = s->nch;
    while (true) {
        int i = 0;
        if (lid == 0) i = atomicAdd(&s->cctr, 1);
        i = __shfl_sync(FULL, i, 0);
        if (i >= nch) break;

        const int g  = s->cg[i];
        const int jl = s->clo[i];
        const int jh = s->chi[i];
        const int base = g * GSIZE;
        const float4 Q0 = s->qpts[base + 2 * lid];
        const float4 Q1 = s->qpts[base + 2 * lid + 1];
        const ull n00 = pack2(-2.0f * Q0.x, -2.0f * Q0.x);
        const ull n10 = pack2(-2.0f * Q0.y, -2.0f * Q0.y);
        const ull n20 = pack2(-2.0f * Q0.z, -2.0f * Q0.z);
        const ull n01 = pack2(-2.0f * Q1.x, -2.0f * Q1.x);
        const ull n11 = pack2(-2.0f * Q1.y, -2.0f * Q1.y);
        const ull n21 = pack2(-2.0f * Q1.z, -2.0f * Q1.z);
        float m00 = FLT_MAX, m10 = FLT_MAX, m01 = FLT_MAX, m11 = FLT_MAX;

        SCAN_RANGE(jl, jh)

        atomicMin(&s->gdist[base + 2 * lid],     fenc(fminf(m00, m10) + Q0.w));
        atomicMin(&s->gdist[base + 2 * lid + 1], fenc(fminf(m01, m11) + Q1.w));
    }
    __syncthreads();

    // ---- Stage C: fixed-order sum of per-query distances ----
    {
        float ssum = 0.0f;
        for (int i = tid; i < QPB; i += THREADS) ssum += fdec(s->gdist[i]);
#pragma unroll
        for (int o = 16; o > 0; o >>= 1) ssum += __shfl_down_sync(FULL, ssum, o);
        if (lid == 0) s->wred[wid] = ssum;
    }
    __syncthreads();
    if (tid == 0) {
        float t = 0.0f;
#pragma unroll
        for (int w = 0; w < NWARP; w++) t += s->wred[w];
        const int lin = blockIdx.x + SPLITS * (blockIdx.y + 2 * blockIdx.z);
        g_partial[lin] = t;
        __threadfence();
        unsigned int old = atomicAdd(&g_ticket, 1u);
        s->amlast = (old == NBLOCKS - 1);
    }
    __syncthreads();

    if (s->amlast) {
        float v = (tid < NBLOCKS) ? g_partial[tid] : 0.0f;
#pragma unroll
        for (int o = 16; o > 0; o >>= 1) v += __shfl_down_sync(FULL, v, o);
        if (lid == 0) s->wred[wid] = v;
        __syncthreads();
        if (tid == 0) {
            float t = 0.0f;
#pragma unroll
            for (int w = 0; w < NWARP; w++) t += s->wred[w];
            out[0] = t * (1.0f / ((float)NB * (float)NPTS));
            g_ticket = 0;
        }
    }
}

extern "C" void kernel_launch(void* const* d_in, const int* in_sizes, int n_in,
                              void* d_out, int out_size)
{
    const float* x = (const float*)d_in[0];
    const float* y = (const float*)d_in[1];
    float* out = (float*)d_out;

    const int smem = (int)sizeof(SmemLayout);   // ~110 KB
    cudaFuncSetAttribute(chamfer_kernel,
                         cudaFuncAttributeMaxDynamicSharedMemorySize, smem);

    sort_kernel<<<NBD, THREADS>>>(x, y);
    dim3 grid(SPLITS, 2, NB);
    chamfer_kernel<<<grid, THREADS, smem>>>(x, y, out);
}

// round 15
// speedup vs baseline: 1.1750x; 1.1750x over previous
#include <cuda_runtime.h>
#include <cfloat>

// ChamferDistance: x,y = [16, 4096, 3] fp32 -> scalar
// R15 = R13 (single kernel: y-sorted window NN + chunked work queue +
//       atomicMin merge) +
//   (a) chunk-skip: each chunk carries y-bounds; at grab time all lanes vote
//       against their CURRENT gdist (which tightens as chunks complete) and
//       provably-useless chunks are skipped,
//   (b) pre-region chunks enqueued near-first so bounds tighten early,
//   (c) warp-shuffle block scans (3 barriers, from R14).
// Exact: skipped chunks cannot contain any improving point. Deterministic:
// the NN's chunk can never be skipped, so the final per-query value is
// bitwise d(q, trueNN) regardless of the (nondeterministic) skip pattern.

#define NB      16
#define NPTS    4096
#define SPLITS  4
#define QPB     (NPTS / SPLITS)   // 1024 queries per block
#define THREADS 512
#define NWARP   (THREADS / 32)    // 16
#define GSIZE   64
#define NGRPB   (QPB / GSIZE)     // 16 groups per block (== NWARP)
#define NBLOCKS (NB * 2 * SPLITS) // 128
#define NBIN    1024
#define BPT     (NBIN / THREADS)  // 2
#define CENT    256
#define CHUNK   512
#define MAXCH   256

__device__ float g_partial[NBLOCKS];
__device__ unsigned int g_ticket;   // zero-init; reset by last block each run

typedef unsigned long long ull;

__device__ __forceinline__ ull pack2(float a, float b) {
    ull r; asm("mov.b64 %0, {%1, %2};" : "=l"(r) : "f"(a), "f"(b)); return r;
}
__device__ __forceinline__ ull fma2(ull a, ull b, ull c) {
    ull d; asm("fma.rn.f32x2 %0, %1, %2, %3;" : "=l"(d) : "l"(a), "l"(b), "l"(c)); return d;
}
__device__ __forceinline__ void unpack2(ull v, float& lo, float& hi) {
    asm("mov.b64 {%0, %1}, %2;" : "=f"(lo), "=f"(hi) : "l"(v));
}
__device__ __forceinline__ unsigned int fenc(float f) {
    unsigned int u = __float_as_uint(f);
    return u ^ (((int)u >> 31) | 0x80000000u);
}
__device__ __forceinline__ float fdec(unsigned int e) {
    unsigned int u = (e & 0x80000000u) ? (e ^ 0x80000000u) : ~e;
    return __uint_as_float(u);
}

struct SmemLayout {
    float  sxa[NPTS];          // y-sorted db SoA
    float  sya[NPTS];
    float  sza[NPTS];
    float  swa[NPTS];          // |p|^2
    float  rlo[NPTS];          // bin lower y-edge per sorted position
    float4 qpts[QPB];          // y-sorted queries (x,y,z,|q|^2)
    int    qidx[QPB];
    unsigned int gdist[QPB];   // per-query encoded min squared distance
    int    dboff[NBIN + 1];
    int    qoff[NBIN + 1];
    int    cnt[NBIN];
    int    cur[NBIN];
    int    ws[NWARP];          // scan workspace
    int    cg[MAXCH];          // chunk -> group
    int    clo[MAXCH], chi[MAXCH];
    float  cylo[MAXCH], cyhi[MAXCH];   // chunk y-bounds (conservative)
    float  wmm[2][NWARP];
    float  wred[NWARP];
    float  ymin, ymax;
    int    nch;
    int    cctr;
    bool   amlast;
};

// Block-wide exclusive prefix sum (3 barriers).
__device__ __forceinline__ int block_exscan(int val, int wid, int lid, int* ws) {
    __syncthreads();
    int incl = val;
#pragma unroll
    for (int o = 1; o < 32; o <<= 1) {
        int n = __shfl_up_sync(0xFFFFFFFFu, incl, o);
        if (lid >= o) incl += n;
    }
    if (lid == 31) ws[wid] = incl;
    __syncthreads();
    if (wid == 0) {
        int wv = (lid < NWARP) ? ws[lid] : 0;
#pragma unroll
        for (int o = 1; o < NWARP; o <<= 1) {
            int n = __shfl_up_sync(0xFFFFFFFFu, wv, o);
            if (lid >= o) wv += n;
        }
        if (lid < NWARP) ws[lid] = wv;
    }
    __syncthreads();
    int wpre = (wid > 0) ? ws[wid - 1] : 0;
    return wpre + incl - val;
}

// Tight vote-free scan: per 4 db pts: 4 LDS.128 + 12 FFMA2 + 8 FMNMX.
#define SCAN_RANGE(JLO, JHI)                                                   \
    _Pragma("unroll 2")                                                        \
    for (int j = (JLO); j < (JHI); j += 4) {                                   \
        const ulonglong2 Xv = *(const ulonglong2*)(s->sxa + j);                \
        const ulonglong2 Yv = *(const ulonglong2*)(s->sya + j);                \
        const ulonglong2 Zv = *(const ulonglong2*)(s->sza + j);                \
        const ulonglong2 Wv = *(const ulonglong2*)(s->swa + j);                \
        ull ta, tb; float e0, e1, f0, f1;                                      \
        ta = fma2(n00, Xv.x, Wv.x); ta = fma2(n10, Yv.x, ta); ta = fma2(n20, Zv.x, ta); \
        tb = fma2(n00, Xv.y, Wv.y); tb = fma2(n10, Yv.y, tb); tb = fma2(n20, Zv.y, tb); \
        unpack2(ta, e0, e1); unpack2(tb, f0, f1);                              \
        m00 = fminf(m00, e0); m00 = fminf(m00, f0);                            \
        m10 = fminf(m10, e1); m10 = fminf(m10, f1);                            \
        ta = fma2(n01, Xv.x, Wv.x); ta = fma2(n11, Yv.x, ta); ta = fma2(n21, Zv.x, ta); \
        tb = fma2(n01, Xv.y, Wv.y); tb = fma2(n11, Yv.y, tb); tb = fma2(n21, Zv.y, tb); \
        unpack2(ta, e0, e1); unpack2(tb, f0, f1);                              \
        m01 = fminf(m01, e0); m01 = fminf(m01, f0);                            \
        m11 = fminf(m11, e1); m11 = fminf(m11, f1);                            \
    }

__global__ __launch_bounds__(THREADS, 1) void chamfer_kernel(
    const float* __restrict__ x, const float* __restrict__ y,
    float* __restrict__ out)
{
    extern __shared__ char sraw[];
    SmemLayout* s = (SmemLayout*)sraw;

    const int tid = threadIdx.x;
    const int wid = tid >> 5, lid = tid & 31;
    const unsigned FULL = 0xFFFFFFFFu;
    const int dir = blockIdx.y;
    const int b   = blockIdx.z;
    const float* __restrict__ q  = (dir ? y : x) + (size_t)b * NPTS * 3
                                   + (size_t)blockIdx.x * QPB * 3;
    const float* __restrict__ db = (dir ? x : y) + (size_t)b * NPTS * 3;

    // ---- y min/max of db ----
    float lmin = FLT_MAX, lmax = -FLT_MAX;
    for (int j = tid; j < NPTS; j += THREADS) {
        float py = db[3 * j + 1];
        lmin = fminf(lmin, py); lmax = fmaxf(lmax, py);
    }
#pragma unroll
    for (int o = 16; o > 0; o >>= 1) {
        lmin = fminf(lmin, __shfl_xor_sync(FULL, lmin, o));
        lmax = fmaxf(lmax, __shfl_xor_sync(FULL, lmax, o));
    }
    if (lid == 0) { s->wmm[0][wid] = lmin; s->wmm[1][wid] = lmax; }
    for (int c = tid; c < NBIN; c += THREADS) s->cnt[c] = 0;
    const unsigned ENC_MAX = fenc(FLT_MAX);
    for (int i = tid; i < QPB; i += THREADS) s->gdist[i] = ENC_MAX;
    __syncthreads();
    if (tid == 0) {
        float a0 = FLT_MAX, a1 = -FLT_MAX;
#pragma unroll
        for (int w = 0; w < NWARP; w++) {
            a0 = fminf(a0, s->wmm[0][w]); a1 = fmaxf(a1, s->wmm[1][w]);
        }
        s->ymin = a0; s->ymax = a1;
        s->nch = 0; s->cctr = 0;
    }
    __syncthreads();

    const float ymin = s->ymin;
    const float W    = fmaxf((s->ymax - ymin) / NBIN, 1e-30f);
    const float inv  = 1.0f / W;

    // ---- db histogram + scan + scatter ----
    for (int j = tid; j < NPTS; j += THREADS) {
        float py = db[3 * j + 1];
        int c = min(max((int)((py - ymin) * inv), 0), NBIN - 1);
        atomicAdd(&s->cnt[c], 1);
    }
    {
        const int base = tid * BPT;
        __syncthreads();
        int c0 = s->cnt[base], c1 = s->cnt[base + 1];
        int ex = block_exscan(c0 + c1, wid, lid, s->ws);
        s->dboff[base]     = ex;
        s->dboff[base + 1] = ex + c0;
        s->cur[base]       = ex;
        s->cur[base + 1]   = ex + c0;
        if (tid == THREADS - 1) s->dboff[NBIN] = NPTS;
    }
    __syncthreads();
    for (int j = tid; j < NPTS; j += THREADS) {
        float a = db[3 * j], c = db[3 * j + 1], d = db[3 * j + 2];
        int cb = min(max((int)((c - ymin) * inv), 0), NBIN - 1);
        int pos = atomicAdd(&s->cur[cb], 1);
        s->sxa[pos] = a; s->sya[pos] = c; s->sza[pos] = d;
        s->swa[pos] = fmaf(a, a, fmaf(c, c, d * d));
        s->rlo[pos] = ymin + (float)cb * W;   // monotone over positions
    }
    __syncthreads();

    // ---- query histogram + scan + scatter + stable intra-bin fix ----
    for (int c = tid; c < NBIN; c += THREADS) s->cnt[c] = 0;
    __syncthreads();
    for (int j = tid; j < QPB; j += THREADS) {
        float py = q[3 * j + 1];
        int c = min(max((int)((py - ymin) * inv), 0), NBIN - 1);
        atomicAdd(&s->cnt[c], 1);
    }
    {
        const int base = tid * BPT;
        __syncthreads();
        int c0 = s->cnt[base], c1 = s->cnt[base + 1];
        int ex = block_exscan(c0 + c1, wid, lid, s->ws);
        s->qoff[base]     = ex;
        s->qoff[base + 1] = ex + c0;
        s->cur[base]      = ex;
        s->cur[base + 1]  = ex + c0;
        if (tid == THREADS - 1) s->qoff[NBIN] = QPB;
    }
    __syncthreads();
    for (int j = tid; j < QPB; j += THREADS) {
        float a = q[3 * j], c = q[3 * j + 1], d = q[3 * j + 2];
        int cb = min(max((int)((c - ymin) * inv), 0), NBIN - 1);
        int pos = atomicAdd(&s->cur[cb], 1);
        s->qpts[pos] = make_float4(a, c, d, fmaf(a, a, fmaf(c, c, d * d)));
        s->qidx[pos] = j;
    }
    __syncthreads();
    for (int c = tid; c < NBIN; c += THREADS) {   // stable fix (bins tiny)
        int lo = s->qoff[c], hi = s->qoff[c + 1];
        for (int i = lo + 1; i < hi; i++) {
            float4 pv = s->qpts[i]; int iv = s->qidx[i];
            int j2 = i - 1;
            while (j2 >= lo && s->qidx[j2] > iv) {
                s->qpts[j2 + 1] = s->qpts[j2];
                s->qidx[j2 + 1] = s->qidx[j2];
                j2--;
            }
            s->qpts[j2 + 1] = pv; s->qidx[j2 + 1] = iv;
        }
    }
    __syncthreads();

    // ---- Stage A: warp w: group w's slab scan -> bound -> enqueue chunks ----
    {
        const int g = wid;
        const int base = g * GSIZE;
        const float4 Q0 = s->qpts[base + 2 * lid];
        const float4 Q1 = s->qpts[base + 2 * lid + 1];
        const ull n00 = pack2(-2.0f * Q0.x, -2.0f * Q0.x);
        const ull n10 = pack2(-2.0f * Q0.y, -2.0f * Q0.y);
        const ull n20 = pack2(-2.0f * Q0.z, -2.0f * Q0.z);
        const ull n01 = pack2(-2.0f * Q1.x, -2.0f * Q1.x);
        const ull n11 = pack2(-2.0f * Q1.y, -2.0f * Q1.y);
        const ull n21 = pack2(-2.0f * Q1.z, -2.0f * Q1.z);
        float m00 = FLT_MAX, m10 = FLT_MAX, m01 = FLT_MAX, m11 = FLT_MAX;

        const float ylo_g = __shfl_sync(FULL, Q0.y, 0);
        const float yhi_g = __shfl_sync(FULL, Q1.y, 31);
        const float ymid  = 0.5f * (ylo_g + yhi_g);
        const int   cbin  = min(max((int)((ymid - ymin) * inv), 0), NBIN - 1);
        int lo_c = s->dboff[cbin] - CENT / 2;
        lo_c = min(max(lo_c, 0), NPTS - CENT) & ~3;
        const int hi_c = lo_c + CENT;
        SCAN_RANGE(lo_c, hi_c)

        const float da  = fminf(m00, m10) + Q0.w;
        const float dbq = fminf(m01, m11) + Q1.w;
        atomicMin(&s->gdist[base + 2 * lid],     fenc(da));
        atomicMin(&s->gdist[base + 2 * lid + 1], fenc(dbq));

        const float d0 = sqrtf(fmaxf(da, 0.0f));
        const float d1 = sqrtf(fmaxf(dbq, 0.0f));
        float wlo = fminf(Q0.y - d0, Q1.y - d1);
        float whi = fmaxf(Q0.y + d0, Q1.y + d1);
#pragma unroll
        for (int o = 16; o > 0; o >>= 1) {
            wlo = fminf(wlo, __shfl_xor_sync(FULL, wlo, o));
            whi = fmaxf(whi, __shfl_xor_sync(FULL, whi, o));
        }
        const int lob = (int)fmaxf(floorf((wlo - ymin) * inv) - 2.0f, 0.0f);
        const int hib = (int)fminf(floorf((whi - ymin) * inv) + 2.0f, (float)(NBIN - 1));
        const int jlo = s->dboff[lob] & ~3;
        const int jhi = min((s->dboff[hib + 1] + 3) & ~3, NPTS);
        const int preh  = min(lo_c, jhi);
        const int postl = max(hi_c, jlo);

        if (lid == 0) {
            int npre  = (preh > jlo)  ? (preh - jlo + CHUNK - 1) / CHUNK : 0;
            int npost = (jhi > postl) ? (jhi - postl + CHUNK - 1) / CHUNK : 0;
            int slot = atomicAdd(&s->nch, npre + npost);
            // pre region: enqueue NEAR-FIRST (downward from preh)
            for (int k = 0; k < npre; k++) {
                int hi = preh - k * CHUNK;
                int lo = max(hi - CHUNK, jlo);
                s->cg[slot]   = g;
                s->clo[slot]  = lo;
                s->chi[slot]  = hi;
                s->cylo[slot] = s->rlo[lo] - W;
                s->cyhi[slot] = s->rlo[hi - 1] + 2.0f * W;
                slot++;
            }
            // post region: near-first is natural (upward from postl)
            for (int k = 0; k < npost; k++) {
                int lo = postl + k * CHUNK;
                int hi = min(lo + CHUNK, jhi);
                s->cg[slot]   = g;
                s->clo[slot]  = lo;
                s->chi[slot]  = hi;
                s->cylo[slot] = s->rlo[lo] - W;
                s->cyhi[slot] = s->rlo[hi - 1] + 2.0f * W;
                slot++;
            }
        }
    }
    __syncthreads();

    // ---- Stage B: dynamic chunk processing with live skip votes ----
    const int nch = s->nch;
    while (true) {
        int i = 0;
        if (lid == 0) i = atomicAdd(&s->cctr, 1);
        i = __shfl_sync(FULL, i, 0);
        if (i >= nch) break;

        const int g  = s->cg[i];
        const int base = g * GSIZE;
        const float4 Q0 = s->qpts[base + 2 * lid];
        const float4 Q1 = s->qpts[base + 2 * lid + 1];

        // live skip vote: can this chunk improve any lane's CURRENT best?
        {
            const float ylo_c = s->cylo[i], yhi_c = s->cyhi[i];
            const float cb0 = fdec(s->gdist[base + 2 * lid]);
            const float cb1 = fdec(s->gdist[base + 2 * lid + 1]);
            const float gap0 = fmaxf(fmaxf(ylo_c - Q0.y, Q0.y - yhi_c), 0.0f);
            const float gap1 = fmaxf(fmaxf(ylo_c - Q1.y, Q1.y - yhi_c), 0.0f);
            const bool useless = (gap0 * gap0 >= cb0) && (gap1 * gap1 >= cb1);
            if (__all_sync(FULL, useless)) continue;
        }

        const int jl = s->clo[i];
        const int jh = s->chi[i];
        const ull n00 = pack2(-2.0f * Q0.x, -2.0f * Q0.x);
        const ull n10 = pack2(-2.0f * Q0.y, -2.0f * Q0.y);
        const ull n20 = pack2(-2.0f * Q0.z, -2.0f * Q0.z);
        const ull n01 = pack2(-2.0f * Q1.x, -2.0f * Q1.x);
        const ull n11 = pack2(-2.0f * Q1.y, -2.0f * Q1.y);
        const ull n21 = pack2(-2.0f * Q1.z, -2.0f * Q1.z);
        float m00 = FLT_MAX, m10 = FLT_MAX, m01 = FLT_MAX, m11 = FLT_MAX;

        SCAN_RANGE(jl, jh)

        atomicMin(&s->gdist[base + 2 * lid],     fenc(fminf(m00, m10) + Q0.w));
        atomicMin(&s->gdist[base + 2 * lid + 1], fenc(fminf(m01, m11) + Q1.w));
    }
    __syncthreads();

    // ---- Stage C: fixed-order sum of per-query distances ----
    {
        float ssum = 0.0f;
        for (int i = tid; i < QPB; i += THREADS) ssum += fdec(s->gdist[i]);
#pragma unroll
        for (int o = 16; o > 0; o >>= 1) ssum += __shfl_down_sync(FULL, ssum, o);
        if (lid == 0) s->wred[wid] = ssum;
    }
    __syncthreads();
    if (tid == 0) {
        float t = 0.0f;
#pragma unroll
        for (int w = 0; w < NWARP; w++) t += s->wred[w];
        const int lin = blockIdx.x + SPLITS * (blockIdx.y + 2 * blockIdx.z);
        g_partial[lin] = t;
        __threadfence();
        unsigned int old = atomicAdd(&g_ticket, 1u);
        s->amlast = (old == NBLOCKS - 1);
    }
    __syncthreads();

    if (s->amlast) {
        float v = (tid < NBLOCKS) ? g_partial[tid] : 0.0f;
#pragma unroll
        for (int o = 16; o > 0; o >>= 1) v += __shfl_down_sync(FULL, v, o);
        if (lid == 0) s->wred[wid] = v;
        __syncthreads();
        if (tid == 0) {
            float t = 0.0f;
#pragma unroll
            for (int w = 0; w < NWARP; w++) t += s->wred[w];
            out[0] = t * (1.0f / ((float)NB * (float)NPTS));
            g_ticket = 0;
        }
    }
}

extern "C" void kernel_launch(void* const* d_in, const int* in_sizes, int n_in,
                              void* d_out, int out_size)
{
    const float* x = (const float*)d_in[0];
    const float* y = (const float*)d_in[1];
    float* out = (float*)d_out;

    const int smem = (int)sizeof(SmemLayout);   // ~129 KB
    cudaFuncSetAttribute(chamfer_kernel,
                         cudaFuncAttributeMaxDynamicSharedMemorySize, smem);

    dim3 grid(SPLITS, 2, NB);
    chamfer_kernel<<<grid, THREADS, smem>>>(x, y, out);
}